// round 2
// baseline (speedup 1.0000x reference)
#include <cuda_runtime.h>

// ---------------------------------------------------------------------------
// Leaky CTRNN, 2 layers. B=64, T=512, D_IN=256, H=1024, D_OUT=256, alpha=0.1
//
// Plan:
//   1) gemm_in0: xin0[t][b][h] = x[b,t,:] @ W_in0[h,:] + b0[h]   (parallel)
//   2) 513 step kernels: kernel s computes layer0(t=s) and layer1(t=s-1),
//      which are mutually independent. Each layer's [64,1024]x[1024,1024]
//      GEMM is split over N-tiles (16 cols) and K-chunks (512) for occupancy;
//      the last K-chunk block per tile (atomic ticket) sums partials, applies
//      the leaky update + ReLU, writes states (into d_out) and v scratch.
//   3) gemm_out: output = states1 @ W_out^T + b_out                (parallel)
// ---------------------------------------------------------------------------

namespace {
constexpr int B    = 64;
constexpr int T    = 512;
constexpr int DIN  = 256;
constexpr int H    = 1024;
constexpr int DOUT = 256;
constexpr float ALPHA_F = 0.1f;
constexpr float OMA_F   = 0.9f;

constexpr int BN  = 16;        // n-tile width in step kernel
constexpr int NT  = H / BN;    // 64 tiles
constexpr int KCH = 512;       // k-chunk length
}

// Scratch (allocation-free rule: __device__ globals)
__device__ float    g_xin0[(size_t)T * B * H];   // [t][b][h], 128 MB
__device__ float    g_v0[B * H];
__device__ float    g_v1[B * H];
__device__ float    g_part0[2][B * H];           // layer0 split-K partials
__device__ float    g_part1[4][B * H];           // layer1 split-K partials
__device__ unsigned g_cnt0[NT];                  // zero-init; reset by finisher
__device__ unsigned g_cnt1[NT];

// ---------------------------------------------------------------------------
// Step kernel: grid = nb0 (layer0 blocks) + nb1 (layer1 blocks), 64 thr/block.
// Tile: 64(M) x 16(N), K-chunk 512, BK=32, micro-tile 4x4 per thread.
// ---------------------------------------------------------------------------
__global__ void __launch_bounds__(64)
step_kernel(int s, int nb0,
            const float* __restrict__ Wrec0,
            const float* __restrict__ Win1,
            const float* __restrict__ Wrec1,
            const float* __restrict__ b1,
            float* __restrict__ states0,   // [B][T][H] region of d_out
            float* __restrict__ states1)   // [B][T][H] region of d_out
{
    __shared__ float aS[32 * 64];   // aS[k*64 + m]
    __shared__ float bS[32 * 16];   // bS[k*16 + n]
    __shared__ unsigned s_last;

    const int tid  = threadIdx.x;
    const bool isL0 = ((int)blockIdx.x) < nb0;
    const int idx   = isL0 ? (int)blockIdx.x : ((int)blockIdx.x - nb0);
    const int tile  = idx & (NT - 1);
    const int chunk = idx / NT;
    const int n0    = tile * BN;
    const int t1    = s - 1;           // layer1 timestep

    const float* A = nullptr;          // activations [64 rows, stride T*H]
    const float* W = nullptr;          // weights     [H rows,  stride H]
    int koff = 0;
    int KC;
    if (isL0) {
        KC = 2;
        koff = chunk * KCH;
        W = Wrec0;
        if (s > 0) A = states0 + (size_t)(s - 1) * H;      // fr0[t=s-1]
    } else {
        KC = 4;
        if (chunk < 2) {
            koff = chunk * KCH;
            W = Wrec1;
            if (t1 > 0) A = states1 + (size_t)(t1 - 1) * H; // fr1[t1-1]
        } else {
            koff = (chunk - 2) * KCH;
            W = Win1;
            A = states0 + (size_t)t1 * H;                   // fr0[t1]
        }
    }

    const int tm4 = (tid >> 2) * 4;    // m base: 0..60
    const int tn4 = (tid & 3) * 4;     // n base within tile: 0..12

    float acc[4][4] = {};

    if (A != nullptr) {
        const float* arow = A + (size_t)tid * ((size_t)T * H) + koff;
        const int ln  = tid & 15;
        const int lkb = (tid >> 4) * 8;
        const float* wrow = W + (size_t)(n0 + ln) * H + koff + lkb;

        for (int k0 = 0; k0 < KCH; k0 += 32) {
            float4 av[8];
            #pragma unroll
            for (int c = 0; c < 8; c++)
                av[c] = *(const float4*)(arow + k0 + c * 4);
            float4 bv0 = *(const float4*)(wrow + k0);
            float4 bv1 = *(const float4*)(wrow + k0 + 4);

            __syncthreads();
            #pragma unroll
            for (int c = 0; c < 8; c++) {
                aS[(c * 4 + 0) * 64 + tid] = av[c].x;
                aS[(c * 4 + 1) * 64 + tid] = av[c].y;
                aS[(c * 4 + 2) * 64 + tid] = av[c].z;
                aS[(c * 4 + 3) * 64 + tid] = av[c].w;
            }
            bS[(lkb + 0) * 16 + ln] = bv0.x;
            bS[(lkb + 1) * 16 + ln] = bv0.y;
            bS[(lkb + 2) * 16 + ln] = bv0.z;
            bS[(lkb + 3) * 16 + ln] = bv0.w;
            bS[(lkb + 4) * 16 + ln] = bv1.x;
            bS[(lkb + 5) * 16 + ln] = bv1.y;
            bS[(lkb + 6) * 16 + ln] = bv1.z;
            bS[(lkb + 7) * 16 + ln] = bv1.w;
            __syncthreads();

            #pragma unroll
            for (int kk = 0; kk < 32; kk++) {
                float4 a = *(const float4*)&aS[kk * 64 + tm4];
                float4 b = *(const float4*)&bS[kk * 16 + tn4];
                acc[0][0] += a.x * b.x; acc[0][1] += a.x * b.y;
                acc[0][2] += a.x * b.z; acc[0][3] += a.x * b.w;
                acc[1][0] += a.y * b.x; acc[1][1] += a.y * b.y;
                acc[1][2] += a.y * b.z; acc[1][3] += a.y * b.w;
                acc[2][0] += a.z * b.x; acc[2][1] += a.z * b.y;
                acc[2][2] += a.z * b.z; acc[2][3] += a.z * b.w;
                acc[3][0] += a.w * b.x; acc[3][1] += a.w * b.y;
                acc[3][2] += a.w * b.z; acc[3][3] += a.w * b.w;
            }
        }
    }

    // Write this chunk's partial tile (disjoint slots -> deterministic).
    {
        float* part = isL0 ? g_part0[chunk] : g_part1[chunk];
        #pragma unroll
        for (int i = 0; i < 4; i++) {
            float4 v = make_float4(acc[i][0], acc[i][1], acc[i][2], acc[i][3]);
            *(float4*)&part[(size_t)(tm4 + i) * H + n0 + tn4] = v;
        }
    }

    __threadfence();
    __syncthreads();
    unsigned* cnt = isL0 ? &g_cnt0[tile] : &g_cnt1[tile];
    if (tid == 0) {
        unsigned old = atomicAdd(cnt, 1u);
        s_last = (old == (unsigned)(KC - 1)) ? 1u : 0u;
        if (s_last) *cnt = 0;   // reset for the next launch (all KC arrived)
    }
    __syncthreads();
    if (!s_last) return;
    __threadfence();

    // --- Finisher: sum partials, leaky update, ReLU, write states + v ---
    if (isL0) {
        #pragma unroll
        for (int i = 0; i < 4; i++) {
            const int m = tm4 + i;
            const size_t off = (size_t)m * H + n0 + tn4;
            float4 p0  = *(const float4*)&g_part0[0][off];
            float4 p1  = *(const float4*)&g_part0[1][off];
            float4 xin = *(const float4*)&g_xin0[((size_t)s * B + m) * H + n0 + tn4];
            float4 vp = make_float4(0.f, 0.f, 0.f, 0.f);
            if (s > 0) vp = *(const float4*)&g_v0[off];
            float4 v;
            v.x = OMA_F * vp.x + ALPHA_F * (p0.x + p1.x + xin.x);
            v.y = OMA_F * vp.y + ALPHA_F * (p0.y + p1.y + xin.y);
            v.z = OMA_F * vp.z + ALPHA_F * (p0.z + p1.z + xin.z);
            v.w = OMA_F * vp.w + ALPHA_F * (p0.w + p1.w + xin.w);
            *(float4*)&g_v0[off] = v;
            float4 fr = make_float4(fmaxf(v.x, 0.f), fmaxf(v.y, 0.f),
                                    fmaxf(v.z, 0.f), fmaxf(v.w, 0.f));
            *(float4*)&states0[((size_t)m * T + s) * H + n0 + tn4] = fr;
        }
    } else {
        float4 bb = *(const float4*)&b1[n0 + tn4];
        #pragma unroll
        for (int i = 0; i < 4; i++) {
            const int m = tm4 + i;
            const size_t off = (size_t)m * H + n0 + tn4;
            float4 p0 = *(const float4*)&g_part1[0][off];
            float4 p1 = *(const float4*)&g_part1[1][off];
            float4 p2 = *(const float4*)&g_part1[2][off];
            float4 p3 = *(const float4*)&g_part1[3][off];
            float4 vp = make_float4(0.f, 0.f, 0.f, 0.f);
            if (t1 > 0) vp = *(const float4*)&g_v1[off];
            float4 v;
            v.x = OMA_F * vp.x + ALPHA_F * (p0.x + p1.x + p2.x + p3.x + bb.x);
            v.y = OMA_F * vp.y + ALPHA_F * (p0.y + p1.y + p2.y + p3.y + bb.y);
            v.z = OMA_F * vp.z + ALPHA_F * (p0.z + p1.z + p2.z + p3.z + bb.z);
            v.w = OMA_F * vp.w + ALPHA_F * (p0.w + p1.w + p2.w + p3.w + bb.w);
            *(float4*)&g_v1[off] = v;
            float4 fr = make_float4(fmaxf(v.x, 0.f), fmaxf(v.y, 0.f),
                                    fmaxf(v.z, 0.f), fmaxf(v.w, 0.f));
            *(float4*)&states1[((size_t)m * T + t1) * H + n0 + tn4] = fr;
        }
    }
}

// ---------------------------------------------------------------------------
// gemm_in0: [B*T, DIN] x [H, DIN]^T -> g_xin0[t][b][h] (+ b0)
// Tile 64x64, BK=16, 256 threads, 4x4 micro-tile.
// ---------------------------------------------------------------------------
__global__ void __launch_bounds__(256)
gemm_in0_kernel(const float* __restrict__ x,
                const float* __restrict__ Win0,
                const float* __restrict__ b0)
{
    __shared__ float aS[16 * 64];
    __shared__ float bS[16 * 64];
    const int tid = threadIdx.x;
    const int m0 = blockIdx.x * 64;
    const int n0 = blockIdx.y * 64;
    const int lr = tid >> 2;
    const int lk = (tid & 3) * 4;
    const int tm4 = (tid >> 4) * 4;
    const int tn4 = (tid & 15) * 4;
    float acc[4][4] = {};
    const float* ap = x    + (size_t)(m0 + lr) * DIN + lk;
    const float* bp = Win0 + (size_t)(n0 + lr) * DIN + lk;

    for (int k0 = 0; k0 < DIN; k0 += 16) {
        float4 av = *(const float4*)(ap + k0);
        float4 bv = *(const float4*)(bp + k0);
        __syncthreads();
        aS[(lk + 0) * 64 + lr] = av.x; aS[(lk + 1) * 64 + lr] = av.y;
        aS[(lk + 2) * 64 + lr] = av.z; aS[(lk + 3) * 64 + lr] = av.w;
        bS[(lk + 0) * 64 + lr] = bv.x; bS[(lk + 1) * 64 + lr] = bv.y;
        bS[(lk + 2) * 64 + lr] = bv.z; bS[(lk + 3) * 64 + lr] = bv.w;
        __syncthreads();
        #pragma unroll
        for (int kk = 0; kk < 16; kk++) {
            float4 a = *(const float4*)&aS[kk * 64 + tm4];
            float4 b = *(const float4*)&bS[kk * 64 + tn4];
            acc[0][0] += a.x * b.x; acc[0][1] += a.x * b.y;
            acc[0][2] += a.x * b.z; acc[0][3] += a.x * b.w;
            acc[1][0] += a.y * b.x; acc[1][1] += a.y * b.y;
            acc[1][2] += a.y * b.z; acc[1][3] += a.y * b.w;
            acc[2][0] += a.z * b.x; acc[2][1] += a.z * b.y;
            acc[2][2] += a.z * b.z; acc[2][3] += a.z * b.w;
            acc[3][0] += a.w * b.x; acc[3][1] += a.w * b.y;
            acc[3][2] += a.w * b.z; acc[3][3] += a.w * b.w;
        }
    }

    float4 bb = *(const float4*)&b0[n0 + tn4];
    #pragma unroll
    for (int i = 0; i < 4; i++) {
        int gm = m0 + tm4 + i;
        int bidx = gm >> 9;          // / T
        int tidx = gm & (T - 1);     // % T
        float4 o;
        o.x = acc[i][0] + bb.x; o.y = acc[i][1] + bb.y;
        o.z = acc[i][2] + bb.z; o.w = acc[i][3] + bb.w;
        *(float4*)&g_xin0[((size_t)tidx * B + bidx) * H + n0 + tn4] = o;
    }
}

// ---------------------------------------------------------------------------
// gemm_out: [B*T, H] x [DOUT, H]^T -> out (+ b_out). Same tiling, K=1024.
// ---------------------------------------------------------------------------
__global__ void __launch_bounds__(256)
gemm_out_kernel(const float* __restrict__ states1,
                const float* __restrict__ Wout,
                const float* __restrict__ bout,
                float* __restrict__ out)
{
    __shared__ float aS[16 * 64];
    __shared__ float bS[16 * 64];
    const int tid = threadIdx.x;
    const int m0 = blockIdx.x * 64;
    const int n0 = blockIdx.y * 64;
    const int lr = tid >> 2;
    const int lk = (tid & 3) * 4;
    const int tm4 = (tid >> 4) * 4;
    const int tn4 = (tid & 15) * 4;
    float acc[4][4] = {};
    const float* ap = states1 + (size_t)(m0 + lr) * H + lk;
    const float* bp = Wout    + (size_t)(n0 + lr) * H + lk;

    for (int k0 = 0; k0 < H; k0 += 16) {
        float4 av = *(const float4*)(ap + k0);
        float4 bv = *(const float4*)(bp + k0);
        __syncthreads();
        aS[(lk + 0) * 64 + lr] = av.x; aS[(lk + 1) * 64 + lr] = av.y;
        aS[(lk + 2) * 64 + lr] = av.z; aS[(lk + 3) * 64 + lr] = av.w;
        bS[(lk + 0) * 64 + lr] = bv.x; bS[(lk + 1) * 64 + lr] = bv.y;
        bS[(lk + 2) * 64 + lr] = bv.z; bS[(lk + 3) * 64 + lr] = bv.w;
        __syncthreads();
        #pragma unroll
        for (int kk = 0; kk < 16; kk++) {
            float4 a = *(const float4*)&aS[kk * 64 + tm4];
            float4 b = *(const float4*)&bS[kk * 64 + tn4];
            acc[0][0] += a.x * b.x; acc[0][1] += a.x * b.y;
            acc[0][2] += a.x * b.z; acc[0][3] += a.x * b.w;
            acc[1][0] += a.y * b.x; acc[1][1] += a.y * b.y;
            acc[1][2] += a.y * b.z; acc[1][3] += a.y * b.w;
            acc[2][0] += a.z * b.x; acc[2][1] += a.z * b.y;
            acc[2][2] += a.z * b.z; acc[2][3] += a.z * b.w;
            acc[3][0] += a.w * b.x; acc[3][1] += a.w * b.y;
            acc[3][2] += a.w * b.z; acc[3][3] += a.w * b.w;
        }
    }

    float4 bb = *(const float4*)&bout[n0 + tn4];
    #pragma unroll
    for (int i = 0; i < 4; i++) {
        int gm = m0 + tm4 + i;
        float4 o;
        o.x = acc[i][0] + bb.x; o.y = acc[i][1] + bb.y;
        o.z = acc[i][2] + bb.z; o.w = acc[i][3] + bb.w;
        *(float4*)&out[(size_t)gm * DOUT + n0 + tn4] = o;
    }
}

// ---------------------------------------------------------------------------
extern "C" void kernel_launch(void* const* d_in, const int* in_sizes, int n_in,
                              void* d_out, int out_size)
{
    (void)in_sizes; (void)n_in; (void)out_size;
    const float* x     = (const float*)d_in[0];
    const float* Win0  = (const float*)d_in[1];
    const float* Wrec0 = (const float*)d_in[2];
    const float* b0    = (const float*)d_in[3];
    const float* Win1  = (const float*)d_in[4];
    const float* Wrec1 = (const float*)d_in[5];
    const float* b1    = (const float*)d_in[6];
    const float* Wout  = (const float*)d_in[7];
    const float* bout  = (const float*)d_in[8];

    float* out     = (float*)d_out;                       // [B][T][DOUT]
    float* states0 = out + (size_t)B * T * DOUT;          // [B][T][H]
    float* states1 = states0 + (size_t)B * T * H;         // [B][T][H]

    // 1) Precompute input projection for all timesteps.
    gemm_in0_kernel<<<dim3((B * T) / 64, H / 64), 256>>>(x, Win0, b0);

    // 2) Sequential scan, pipelined: kernel s does layer0(s) + layer1(s-1).
    for (int s = 0; s <= T; s++) {
        const int nb0 = (s < T) ? 2 * NT : 0;   // layer0: 64 tiles x 2 chunks
        const int nb1 = (s >= 1) ? 4 * NT : 0;  // layer1: 64 tiles x 4 chunks
        step_kernel<<<nb0 + nb1, 64>>>(s, nb0, Wrec0, Win1, Wrec1, b1,
                                       states0, states1);
    }

    // 3) Output projection.
    gemm_out_kernel<<<dim3((B * T) / 64, DOUT / 64), 256>>>(states1, Wout,
                                                            bout, out);
}

// round 3
// speedup vs baseline: 2.2762x; 2.2762x over previous
#include <cuda_runtime.h>

// ---------------------------------------------------------------------------
// Leaky CTRNN, persistent-kernel scan. B=64, T=512, D_IN=256, H=1024, D_OUT=256
//
//  k1: gemm_in0  — xin0[t][h][b] = W_in0 @ x[:,t,:]^T + b0   (coalesced store)
//  k2: rnn_persistent — 96 blocks (1/SM, co-resident), 514 phases,
//      one grid barrier per phase:
//        role0 (blk  0-31): fr0(p)  = relu(v0 = .9 v0 + .1(fr0(p-1)@Wrec0^T + xin0))
//        role1 (blk 32-63): pin(p-1)= fr0(p-1)@Win1^T + b1
//        role2 (blk 64-95): fr1(p-2)= relu(v1 = .9 v1 + .1(fr1(p-3)@Wrec1^T + pin))
//      Weights persist in smem (32 cols/block); v in registers; activations in
//      transposed [slot][h][b] global rings staged via cp.async.cg (L1-bypass);
//      math in packed fma.rn.f32x2.
//  k3: gemm_out — output = states1 @ W_out^T + b_out
// ---------------------------------------------------------------------------

namespace {
constexpr int B = 64, T = 512, DIN = 256, H = 1024, DOUT = 256;
constexpr float AL = 0.1f, OMA = 0.9f;

constexpr int NBLK = 96;           // persistent blocks (<=148 SMs, 1 per SM)
constexpr int THR  = 256;
constexpr int NCOL = 32;           // weight columns per block
constexpr int KC   = 128;          // k-chunk
constexpr int NCH  = H / KC;       // 8
constexpr int ABUF = 2 * KC * B;   // double-buffered A staging (floats)
constexpr int SMEM_P = (ABUF + H * NCOL) * 4;   // 64KB + 128KB = 192KB
}

// Scratch (allocation-free rule: __device__ globals)
__device__ float g_xin0[(size_t)T * H * B];     // [t][h][b]
__device__ float g_fr0[2 * (size_t)H * B];      // ring [t&1][h][b]
__device__ float g_fr1[2 * (size_t)H * B];
__device__ float g_pin[2 * (size_t)H * B];
__device__ volatile unsigned g_gen;
__device__ unsigned g_cnt;

// ---- packed fp32x2 + async-copy helpers -----------------------------------
__device__ __forceinline__ unsigned long long dup2(float x) {
    unsigned long long d;
    asm("mov.b64 %0, {%1, %1};" : "=l"(d) : "r"(__float_as_uint(x)));
    return d;
}
__device__ __forceinline__ void fma2(unsigned long long& a,
                                     unsigned long long x, unsigned long long y) {
    asm("fma.rn.f32x2 %0, %1, %2, %0;" : "+l"(a) : "l"(x), "l"(y));
}
__device__ __forceinline__ float2 unpk(unsigned long long v) {
    unsigned lo, hi;
    asm("mov.b64 {%0, %1}, %2;" : "=r"(lo), "=r"(hi) : "l"(v));
    return make_float2(__uint_as_float(lo), __uint_as_float(hi));
}
__device__ __forceinline__ void cp16(float* d, const float* s) {
    unsigned a = (unsigned)__cvta_generic_to_shared(d);
    asm volatile("cp.async.cg.shared.global [%0], [%1], 16;" :: "r"(a), "l"(s));
}
#define CPCOMMIT() asm volatile("cp.async.commit_group;")
#define CPWAIT(n)  asm volatile("cp.async.wait_group %0;" :: "n"(n))

__device__ __forceinline__ void gridbar() {
    __syncthreads();
    if (threadIdx.x == 0) {
        __threadfence();
        unsigned gen = g_gen;
        if (atomicAdd(&g_cnt, 1u) == NBLK - 1) {
            g_cnt = 0;
            __threadfence();
            g_gen = gen + 1;
        } else {
            while (g_gen == gen) {}
            __threadfence();
        }
    }
    __syncthreads();
}

// ---------------------------------------------------------------------------
__global__ void __launch_bounds__(THR, 1)
rnn_persistent(const float* __restrict__ Wrec0, const float* __restrict__ Win1,
               const float* __restrict__ Wrec1, const float* __restrict__ b1,
               float* __restrict__ states0, float* __restrict__ states1)
{
    extern __shared__ float sm[];
    float* aS = sm;                 // [2][KC][B]
    float* wS = sm + ABUF;          // [H][NCOL] k-major

    const int tid  = threadIdx.x;
    const int role = (int)blockIdx.x >> 5;          // 0,1,2
    const int n0   = ((int)blockIdx.x & 31) * NCOL;
    const int tmb  = (tid & 15) * 4;                // batch base (0..60)
    const int tnb  = (tid >> 4) * 2;                // local col pair (0..30)

    // One-time weight load, transposed into smem: wS[k][n] = W[n0+n][k]
    const float* Wsrc = role == 0 ? Wrec0 : (role == 1 ? Win1 : Wrec1);
    for (int it = tid; it < NCOL * (H / 4); it += THR) {
        int n = it & 31, k4 = (it >> 5) << 2;
        float4 w = *(const float4*)(Wsrc + (size_t)(n0 + n) * H + k4);
        wS[(k4 + 0) * NCOL + n] = w.x; wS[(k4 + 1) * NCOL + n] = w.y;
        wS[(k4 + 2) * NCOL + n] = w.z; wS[(k4 + 3) * NCOL + n] = w.w;
    }
    float b1n0 = 0.f, b1n1 = 0.f;
    if (role == 1) { b1n0 = b1[n0 + tnb]; b1n1 = b1[n0 + tnb + 1]; }
    __syncthreads();

    float v[2][4];
    #pragma unroll
    for (int i = 0; i < 2; i++)
        #pragma unroll
        for (int j = 0; j < 4; j++) v[i][j] = 0.f;

    float* states = (role == 0) ? states0 : states1;

    for (int p = 0; p < T + 2; p++) {
        int t; const float* asrc; bool act, dogemm;
        if (role == 0) {
            t = p; act = (t < T); dogemm = act && (p > 0);
            asrc = g_fr0 + (size_t)((p - 1) & 1) * H * B;
        } else if (role == 1) {
            t = p - 1; act = (t >= 0 && t < T); dogemm = act;
            asrc = g_fr0 + (size_t)(t & 1) * H * B;
        } else {
            t = p - 2; act = (t >= 0 && t < T); dogemm = act && (t > 0);
            asrc = g_fr1 + (size_t)((t - 1) & 1) * H * B;
        }

        unsigned long long acc[2][2] = {{0ull, 0ull}, {0ull, 0ull}};

        if (dogemm) {
            #pragma unroll
            for (int j = 0; j < 8; j++) {           // preload chunk 0
                int off = (j * THR + tid) * 4;
                cp16(aS + off, asrc + off);
            }
            CPCOMMIT();
            for (int c = 0; c < NCH; c++) {
                if (c + 1 < NCH) {
                    const float* s = asrc + (size_t)(c + 1) * KC * B;
                    float* d = aS + ((c + 1) & 1) * KC * B;
                    #pragma unroll
                    for (int j = 0; j < 8; j++) {
                        int off = (j * THR + tid) * 4;
                        cp16(d + off, s + off);
                    }
                    CPCOMMIT();
                    CPWAIT(1);
                } else {
                    CPWAIT(0);
                }
                __syncthreads();
                const float* ab = aS + (c & 1) * KC * B + tmb;
                const float* wb = wS + c * KC * NCOL + tnb;
                #pragma unroll 8
                for (int kk = 0; kk < KC; kk++) {
                    ulonglong2 Av = *(const ulonglong2*)(ab + kk * 64);
                    float2 w = *(const float2*)(wb + kk * NCOL);
                    unsigned long long wx = dup2(w.x), wy = dup2(w.y);
                    fma2(acc[0][0], Av.x, wx); fma2(acc[0][1], Av.y, wx);
                    fma2(acc[1][0], Av.x, wy); fma2(acc[1][1], Av.y, wy);
                }
                __syncthreads();
            }
        }

        if (act) {
            if (role == 1) {
                #pragma unroll
                for (int ni = 0; ni < 2; ni++) {
                    float2 a0 = unpk(acc[ni][0]), a1 = unpk(acc[ni][1]);
                    float bb = ni ? b1n1 : b1n0;
                    float4 o = make_float4(a0.x + bb, a0.y + bb,
                                           a1.x + bb, a1.y + bb);
                    *(float4*)&g_pin[(size_t)(t & 1) * H * B +
                                     (size_t)(n0 + tnb + ni) * B + tmb] = o;
                }
            } else {
                float fr[2][4];
                float* ring = (role == 0) ? g_fr0 : g_fr1;
                #pragma unroll
                for (int ni = 0; ni < 2; ni++) {
                    size_t vecoff = (size_t)(n0 + tnb + ni) * B + tmb;
                    float4 add;
                    if (role == 0)
                        add = *(const float4*)&g_xin0[(size_t)t * H * B + vecoff];
                    else
                        add = __ldcg((const float4*)&g_pin[(size_t)(t & 1) * H * B + vecoff]);
                    float2 a0 = unpk(acc[ni][0]), a1 = unpk(acc[ni][1]);
                    v[ni][0] = OMA * v[ni][0] + AL * (a0.x + add.x);
                    v[ni][1] = OMA * v[ni][1] + AL * (a0.y + add.y);
                    v[ni][2] = OMA * v[ni][2] + AL * (a1.x + add.z);
                    v[ni][3] = OMA * v[ni][3] + AL * (a1.y + add.w);
                    float4 f = make_float4(fmaxf(v[ni][0], 0.f), fmaxf(v[ni][1], 0.f),
                                           fmaxf(v[ni][2], 0.f), fmaxf(v[ni][3], 0.f));
                    fr[ni][0] = f.x; fr[ni][1] = f.y; fr[ni][2] = f.z; fr[ni][3] = f.w;
                    *(float4*)&ring[(size_t)(t & 1) * H * B + vecoff] = f;
                }
                #pragma unroll
                for (int bl = 0; bl < 4; bl++) {
                    float2 o = make_float2(fr[0][bl], fr[1][bl]);
                    *(float2*)&states[((size_t)(tmb + bl) * T + t) * H + n0 + tnb] = o;
                }
            }
        }
        if (p < T + 1) gridbar();
    }
}

// ---------------------------------------------------------------------------
// gemm_in0: per timestep t, xin0[t][h][b] = W_in0[h,:] . x[b,t,:] + b0[h]
// grid (H/64, T), tile 64h x 64b, K=256, 256 thr, 4x4 micro-tile.
// ---------------------------------------------------------------------------
__global__ void __launch_bounds__(256)
gemm_in0_kernel(const float* __restrict__ x,
                const float* __restrict__ Win0,
                const float* __restrict__ b0)
{
    __shared__ float aS[16 * 64];
    __shared__ float bS[16 * 64];
    const int tid = threadIdx.x;
    const int m0 = blockIdx.x * 64;     // h
    const int t  = blockIdx.y;
    const int lr = tid >> 2;
    const int lk = (tid & 3) * 4;
    const int tm4 = (tid >> 4) * 4;
    const int tn4 = (tid & 15) * 4;
    float acc[4][4] = {};
    const float* ap = Win0 + (size_t)(m0 + lr) * DIN + lk;
    const float* bp = x + ((size_t)lr * T + t) * DIN + lk;

    for (int k0 = 0; k0 < DIN; k0 += 16) {
        float4 av = *(const float4*)(ap + k0);
        float4 bv = *(const float4*)(bp + k0);
        __syncthreads();
        aS[(lk + 0) * 64 + lr] = av.x; aS[(lk + 1) * 64 + lr] = av.y;
        aS[(lk + 2) * 64 + lr] = av.z; aS[(lk + 3) * 64 + lr] = av.w;
        bS[(lk + 0) * 64 + lr] = bv.x; bS[(lk + 1) * 64 + lr] = bv.y;
        bS[(lk + 2) * 64 + lr] = bv.z; bS[(lk + 3) * 64 + lr] = bv.w;
        __syncthreads();
        #pragma unroll
        for (int kk = 0; kk < 16; kk++) {
            float4 a = *(const float4*)&aS[kk * 64 + tm4];
            float4 b = *(const float4*)&bS[kk * 64 + tn4];
            acc[0][0] += a.x * b.x; acc[0][1] += a.x * b.y;
            acc[0][2] += a.x * b.z; acc[0][3] += a.x * b.w;
            acc[1][0] += a.y * b.x; acc[1][1] += a.y * b.y;
            acc[1][2] += a.y * b.z; acc[1][3] += a.y * b.w;
            acc[2][0] += a.z * b.x; acc[2][1] += a.z * b.y;
            acc[2][2] += a.z * b.z; acc[2][3] += a.z * b.w;
            acc[3][0] += a.w * b.x; acc[3][1] += a.w * b.y;
            acc[3][2] += a.w * b.z; acc[3][3] += a.w * b.w;
        }
    }
    #pragma unroll
    for (int i = 0; i < 4; i++) {
        float bb = b0[m0 + tm4 + i];
        float4 o = make_float4(acc[i][0] + bb, acc[i][1] + bb,
                               acc[i][2] + bb, acc[i][3] + bb);
        *(float4*)&g_xin0[((size_t)t * H + m0 + tm4 + i) * B + tn4] = o;
    }
}

// ---------------------------------------------------------------------------
// gemm_out: output[B*T, DOUT] = states1[B*T, H] @ W_out^T + b_out
// ---------------------------------------------------------------------------
__global__ void __launch_bounds__(256)
gemm_out_kernel(const float* __restrict__ states1,
                const float* __restrict__ Wout,
                const float* __restrict__ bout,
                float* __restrict__ out)
{
    __shared__ float aS[16 * 64];
    __shared__ float bS[16 * 64];
    const int tid = threadIdx.x;
    const int m0 = blockIdx.x * 64;
    const int n0 = blockIdx.y * 64;
    const int lr = tid >> 2;
    const int lk = (tid & 3) * 4;
    const int tm4 = (tid >> 4) * 4;
    const int tn4 = (tid & 15) * 4;
    float acc[4][4] = {};
    const float* ap = states1 + (size_t)(m0 + lr) * H + lk;
    const float* bp = Wout    + (size_t)(n0 + lr) * H + lk;

    for (int k0 = 0; k0 < H; k0 += 16) {
        float4 av = *(const float4*)(ap + k0);
        float4 bv = *(const float4*)(bp + k0);
        __syncthreads();
        aS[(lk + 0) * 64 + lr] = av.x; aS[(lk + 1) * 64 + lr] = av.y;
        aS[(lk + 2) * 64 + lr] = av.z; aS[(lk + 3) * 64 + lr] = av.w;
        bS[(lk + 0) * 64 + lr] = bv.x; bS[(lk + 1) * 64 + lr] = bv.y;
        bS[(lk + 2) * 64 + lr] = bv.z; bS[(lk + 3) * 64 + lr] = bv.w;
        __syncthreads();
        #pragma unroll
        for (int kk = 0; kk < 16; kk++) {
            float4 a = *(const float4*)&aS[kk * 64 + tm4];
            float4 b = *(const float4*)&bS[kk * 64 + tn4];
            acc[0][0] += a.x * b.x; acc[0][1] += a.x * b.y;
            acc[0][2] += a.x * b.z; acc[0][3] += a.x * b.w;
            acc[1][0] += a.y * b.x; acc[1][1] += a.y * b.y;
            acc[1][2] += a.y * b.z; acc[1][3] += a.y * b.w;
            acc[2][0] += a.z * b.x; acc[2][1] += a.z * b.y;
            acc[2][2] += a.z * b.z; acc[2][3] += a.z * b.w;
            acc[3][0] += a.w * b.x; acc[3][1] += a.w * b.y;
            acc[3][2] += a.w * b.z; acc[3][3] += a.w * b.w;
        }
    }
    #pragma unroll
    for (int i = 0; i < 4; i++) {
        float4 bb = *(const float4*)&bout[n0 + tn4];
        int gm = m0 + tm4 + i;
        float4 o = make_float4(acc[i][0] + bb.x, acc[i][1] + bb.y,
                               acc[i][2] + bb.z, acc[i][3] + bb.w);
        *(float4*)&out[(size_t)gm * DOUT + n0 + tn4] = o;
    }
}

// ---------------------------------------------------------------------------
extern "C" void kernel_launch(void* const* d_in, const int* in_sizes, int n_in,
                              void* d_out, int out_size)
{
    (void)in_sizes; (void)n_in; (void)out_size;
    const float* x     = (const float*)d_in[0];
    const float* Win0  = (const float*)d_in[1];
    const float* Wrec0 = (const float*)d_in[2];
    const float* b0    = (const float*)d_in[3];
    const float* Win1  = (const float*)d_in[4];
    const float* Wrec1 = (const float*)d_in[5];
    const float* b1    = (const float*)d_in[6];
    const float* Wout  = (const float*)d_in[7];
    const float* bout  = (const float*)d_in[8];

    float* out     = (float*)d_out;                   // [B][T][DOUT]
    float* states0 = out + (size_t)B * T * DOUT;      // [B][T][H]
    float* states1 = states0 + (size_t)B * T * H;     // [B][T][H]

    cudaFuncSetAttribute(rnn_persistent,
                         cudaFuncAttributeMaxDynamicSharedMemorySize, SMEM_P);

    gemm_in0_kernel<<<dim3(H / 64, T), 256>>>(x, Win0, b0);
    rnn_persistent<<<NBLK, THR, SMEM_P>>>(Wrec0, Win1, Wrec1, b1,
                                          states0, states1);
    gemm_out_kernel<<<dim3((B * T) / 64, DOUT / 64), 256>>>(states1, Wout,
                                                            bout, out);
}